// round 8
// baseline (speedup 1.0000x reference)
#include <cuda_runtime.h>
#include <math.h>
#include <stdint.h>

#define B_   2
#define T_   2048
#define D_   512
#define H_   8
#define HD_  64
#define QKV3 (3 * D_)   // 1536
#define NROW (B_ * T_)  // 4096

__device__ float g_qkv[B_ * T_ * QKV3];
__device__ float g_attn[B_ * T_ * D_];

// ---------------------------------------------------------------------------
// TF32 GEMM v4 (unchanged from round 7): block 128x128, BK=16, 256 thr,
// 8 warps 64x32, double-buffered, pair-interleaved uint2 smem (LDS.64 frags).
// ---------------------------------------------------------------------------
#define MP  132
#define BSZ (8 * MP)

__device__ __forceinline__ uint32_t f2tf32(float x) {
    uint32_t u;
    asm("cvt.rna.tf32.f32 %0, %1;" : "=r"(u) : "f"(x));
    return u;
}

__global__ __launch_bounds__(256)
void gemm_tf32_v4(const float* __restrict__ A, const float* __restrict__ W,
                  const float* __restrict__ bias, float* __restrict__ C,
                  int N, int M, int K)
{
    __shared__ uint2 Asm[2][BSZ];
    __shared__ uint2 Wsm[2][BSZ];

    const int tid  = threadIdx.x;
    const int warp = tid >> 5;
    const int lane = tid & 31;
    const int g    = lane >> 2;
    const int t4   = lane & 3;

    const int n0 = blockIdx.y * 128;
    const int m0 = blockIdx.x * 128;
    const int r0 = (warp >> 2) * 64;
    const int c0 = (warp & 3) * 32;

    const int lrow = tid >> 1;
    const int lg2  = tid & 1;
    const float* Arow = A + (size_t)(n0 + lrow) * K + lg2 * 8;
    const float* Wrow = W + (size_t)(m0 + lrow) * K + lg2 * 8;

    float c[4][4][4];
#pragma unroll
    for (int mi = 0; mi < 4; mi++)
#pragma unroll
        for (int ni = 0; ni < 4; ni++)
#pragma unroll
            for (int q = 0; q < 4; q++) c[mi][ni][q] = 0.f;

    float4 av0, av1, wv0, wv1;

#define LD_TILE(koff)                              \
    av0 = *(const float4*)(Arow + (koff));         \
    av1 = *(const float4*)(Arow + (koff) + 4);     \
    wv0 = *(const float4*)(Wrow + (koff));         \
    wv1 = *(const float4*)(Wrow + (koff) + 4);

#define ST_TILE(buf)                                                  \
    {                                                                 \
        uint2* da = &Asm[(buf)][lg2 * 4 * MP + lrow];                 \
        da[0*MP] = make_uint2(f2tf32(av0.x), f2tf32(av1.x));          \
        da[1*MP] = make_uint2(f2tf32(av0.y), f2tf32(av1.y));          \
        da[2*MP] = make_uint2(f2tf32(av0.z), f2tf32(av1.z));          \
        da[3*MP] = make_uint2(f2tf32(av0.w), f2tf32(av1.w));          \
        uint2* dw = &Wsm[(buf)][lg2 * 4 * MP + lrow];                 \
        dw[0*MP] = make_uint2(f2tf32(wv0.x), f2tf32(wv1.x));          \
        dw[1*MP] = make_uint2(f2tf32(wv0.y), f2tf32(wv1.y));          \
        dw[2*MP] = make_uint2(f2tf32(wv0.z), f2tf32(wv1.z));          \
        dw[3*MP] = make_uint2(f2tf32(wv0.w), f2tf32(wv1.w));          \
    }

    LD_TILE(0);
    ST_TILE(0);
    __syncthreads();

    const int NT = K / 16;
    for (int it = 0; it < NT; it++) {
        if (it + 1 < NT) { LD_TILE((it + 1) * 16); }
        const int buf = it & 1;
#pragma unroll
        for (int g2 = 0; g2 < 2; g2++) {
            const uint2* ab = &Asm[buf][(g2 * 4 + t4) * MP];
            const uint2* wb = &Wsm[buf][(g2 * 4 + t4) * MP];
            uint2 bf[4];
#pragma unroll
            for (int ni = 0; ni < 4; ni++)
                bf[ni] = wb[c0 + ni * 8 + g];
#pragma unroll
            for (int mi = 0; mi < 4; mi++) {
                uint2 aL = ab[r0 + mi * 16 + g];
                uint2 aH = ab[r0 + mi * 16 + g + 8];
#pragma unroll
                for (int ni = 0; ni < 4; ni++) {
                    asm volatile(
                        "mma.sync.aligned.m16n8k8.row.col.f32.tf32.tf32.f32 "
                        "{%0,%1,%2,%3}, {%4,%5,%6,%7}, {%8,%9}, {%0,%1,%2,%3};"
                        : "+f"(c[mi][ni][0]), "+f"(c[mi][ni][1]),
                          "+f"(c[mi][ni][2]), "+f"(c[mi][ni][3])
                        : "r"(aL.x), "r"(aH.x), "r"(aL.y), "r"(aH.y),
                          "r"(bf[ni].x), "r"(bf[ni].y));
                }
            }
        }
        if (it + 1 < NT) {
            __syncthreads();
            ST_TILE((it + 1) & 1);
            __syncthreads();
        }
    }

#pragma unroll
    for (int mi = 0; mi < 4; mi++) {
        int row_a = n0 + r0 + mi * 16 + g;
        int row_b = row_a + 8;
#pragma unroll
        for (int ni = 0; ni < 4; ni++) {
            int col = m0 + c0 + ni * 8 + 2 * t4;
            float bx = bias[col], by = bias[col + 1];
            *(float2*)(C + (size_t)row_a * M + col) =
                make_float2(c[mi][ni][0] + bx, c[mi][ni][1] + by);
            *(float2*)(C + (size_t)row_b * M + col) =
                make_float2(c[mi][ni][2] + bx, c[mi][ni][3] + by);
        }
    }
#undef LD_TILE
#undef ST_TILE
}

// ---------------------------------------------------------------------------
// Residue-class attention v2.
// Block = (bh, r, 16-query tile of class positions). 512 threads = 16 warps
// = 8 query-pairs x 2 key-phases. K/V staged 64 keys/stage at stride 68
// (float4 staging, conflict-free LDS.128 K reads, conflict-free scalar V).
// Each warp serves 2 queries per chunk -> K/V smem reads amortized 2x.
// ---------------------------------------------------------------------------
#define SKV 68          // floats per K/V row (64 + 4 pad, 16B-aligned rows)
#define AQ2 16          // queries per block

__global__ __launch_bounds__(512)
void attn_class_v2(const int* __restrict__ periods)
{
    const int bh = blockIdx.y;
    const int b  = bh >> 3;
    const int h  = bh & 7;
    int p = periods[bh];
    if (p < 1) p = 1;

    const int x    = blockIdx.x;
    const int r    = x % p;
    const int tile = x / p;
    const int c0   = tile * AQ2;
    if (r + c0 * p > T_ - 1) return;

    const int tid  = threadIdx.x;
    const int warp = tid >> 5;
    const int lane = tid & 31;

    const int L    = (T_ - 1 - r) / p + 1;
    const int cmax = min(c0 + AQ2 - 1, L - 1);
    const int nch  = cmax / 32 + 1;

    __shared__ float Ks[64 * SKV];
    __shared__ float Vs[64 * SKV];
    __shared__ float Qs[AQ2][64];
    __shared__ float Cmb[AQ2][66];

    const float* base = g_qkv + (size_t)b * T_ * QKV3;

    // stage scaled Q: 512 threads, each loads 2 floats
    {
        int qi = tid >> 5;            // 0..15
        int d2 = (tid & 31) * 2;
        int cq = c0 + qi;
        float2 qv = make_float2(0.f, 0.f);
        if (cq <= cmax) {
            int iq = r + cq * p;
            const float* qs = base + (size_t)iq * QKV3 + h * HD_ + d2;
            qv = *(const float2*)qs;
            qv.x *= 0.125f; qv.y *= 0.125f;
        }
        Qs[qi][d2]     = qv.x;
        Qs[qi][d2 + 1] = qv.y;
    }

    const int qp   = warp >> 1;       // query pair 0..7
    const int half = warp & 1;        // key phase: even/odd chunks
    const int cq0  = c0 + 2 * qp;
    const int cq1  = cq0 + 1;
    const bool v0  = (cq0 <= cmax);
    const bool v1  = (cq1 <= cmax);
    const int cqH  = v1 ? cq1 : cq0;

    float m0 = -1e30f, l0 = 0.f, a0x = 0.f, a0y = 0.f;
    float m1 = -1e30f, l1 = 0.f, a1x = 0.f, a1y = 0.f;

    const int srow  = tid >> 4;       // 0..31 (stage two rows: srow, srow+32)
    const int spart = tid & 15;       // 0..7 K halves, 8..15 V halves

    const int niter = (nch + 1) >> 1;
    for (int t = 0; t < niter; t++) {
        __syncthreads();
        // stage 64 keys [64t, 64t+64) as float4 (K and V, stride SKV)
#pragma unroll
        for (int rr = 0; rr < 2; rr++) {
            int row = srow + rr * 32;
            int mg  = t * 64 + row;
            if (mg <= cmax) {
                int ik = r + mg * p;
                const float* src = base + (size_t)ik * QKV3 + D_ + h * HD_;
                if (spart < 8) {
                    int c4 = spart * 2;
                    float4 k0 = *(const float4*)(src + c4 * 4);
                    float4 k1 = *(const float4*)(src + c4 * 4 + 4);
                    *(float4*)(&Ks[row * SKV + c4 * 4])     = k0;
                    *(float4*)(&Ks[row * SKV + c4 * 4 + 4]) = k1;
                } else {
                    int c4 = (spart - 8) * 2;
                    float4 vv0 = *(const float4*)(src + D_ + c4 * 4);
                    float4 vv1 = *(const float4*)(src + D_ + c4 * 4 + 4);
                    *(float4*)(&Vs[row * SKV + c4 * 4])     = vv0;
                    *(float4*)(&Vs[row * SKV + c4 * 4 + 4]) = vv1;
                }
            }
        }
        __syncthreads();

        const int ch     = 2 * t + half;
        const int mstart = ch * 32;
        if (v0 && ch < nch && mstart <= cqH) {
            const int rb = half * 32;
            // dot products for both queries (K via LDS.128, Q broadcast)
            const float* krow = &Ks[(rb + lane) * SKV];
            const float* q0p  = Qs[2 * qp];
            const float* q1p  = Qs[2 * qp + 1];
            float s0a = 0.f, s0b = 0.f, s1a = 0.f, s1b = 0.f;
#pragma unroll
            for (int i = 0; i < 16; i += 2) {
                float4 kf = *(const float4*)(krow + 4 * i);
                float4 qa = *(const float4*)(q0p + 4 * i);
                float4 qb = *(const float4*)(q1p + 4 * i);
                s0a = fmaf(kf.x, qa.x, fmaf(kf.y, qa.y, s0a));
                s0a = fmaf(kf.z, qa.z, fmaf(kf.w, qa.w, s0a));
                s1a = fmaf(kf.x, qb.x, fmaf(kf.y, qb.y, s1a));
                s1a = fmaf(kf.z, qb.z, fmaf(kf.w, qb.w, s1a));
                float4 kg = *(const float4*)(krow + 4 * i + 4);
                float4 qc = *(const float4*)(q0p + 4 * i + 4);
                float4 qd = *(const float4*)(q1p + 4 * i + 4);
                s0b = fmaf(kg.x, qc.x, fmaf(kg.y, qc.y, s0b));
                s0b = fmaf(kg.z, qc.z, fmaf(kg.w, qc.w, s0b));
                s1b = fmaf(kg.x, qd.x, fmaf(kg.y, qd.y, s1b));
                s1b = fmaf(kg.z, qd.z, fmaf(kg.w, qd.w, s1b));
            }
            const bool k0ok = (mstart + lane <= cq0);
            const bool k1ok = v1 && (mstart + lane <= cq1);
            float s0 = k0ok ? (s0a + s0b) : -1e30f;
            float s1 = k1ok ? (s1a + s1b) : -1e30f;

            float cm0 = s0, cm1 = s1;
#pragma unroll
            for (int o = 16; o > 0; o >>= 1) {
                cm0 = fmaxf(cm0, __shfl_xor_sync(0xffffffffu, cm0, o));
                cm1 = fmaxf(cm1, __shfl_xor_sync(0xffffffffu, cm1, o));
            }
            float nm0 = fmaxf(m0, cm0);
            float nm1 = fmaxf(m1, cm1);
            float co0 = __expf(m0 - nm0);
            float co1 = __expf(m1 - nm1);
            float pe0 = k0ok ? __expf(s0 - nm0) : 0.f;
            float pe1 = k1ok ? __expf(s1 - nm1) : 0.f;
            float cs0 = pe0, cs1 = pe1;
#pragma unroll
            for (int o = 16; o > 0; o >>= 1) {
                cs0 += __shfl_xor_sync(0xffffffffu, cs0, o);
                cs1 += __shfl_xor_sync(0xffffffffu, cs1, o);
            }
            l0 = l0 * co0 + cs0;
            l1 = l1 * co1 + cs1;

            // V accumulation: shared V reads serve both queries
            const float* vb = &Vs[rb * SKV];
            float A0x = 0.f, A0y = 0.f, A1x = 0.f, A1y = 0.f;
#pragma unroll 4
            for (int j = 0; j < 32; j++) {
                float pj0 = __shfl_sync(0xffffffffu, pe0, j);
                float pj1 = __shfl_sync(0xffffffffu, pe1, j);
                float va = vb[j * SKV + lane];
                float vbv = vb[j * SKV + lane + 32];
                A0x = fmaf(pj0, va, A0x);
                A0y = fmaf(pj0, vbv, A0y);
                A1x = fmaf(pj1, va, A1x);
                A1y = fmaf(pj1, vbv, A1y);
            }
            a0x = fmaf(a0x, co0, A0x);
            a0y = fmaf(a0y, co0, A0y);
            a1x = fmaf(a1x, co1, A1x);
            a1y = fmaf(a1y, co1, A1y);
            m0 = nm0;
            m1 = nm1;
        }
    }

    // combine phases
    __syncthreads();
    if (half == 1 && v0) {
        if (lane == 0) { Cmb[2*qp][0] = m0; Cmb[2*qp][1] = l0; }
        Cmb[2*qp][2 + lane]  = a0x;
        Cmb[2*qp][34 + lane] = a0y;
        if (v1) {
            if (lane == 0) { Cmb[2*qp+1][0] = m1; Cmb[2*qp+1][1] = l1; }
            Cmb[2*qp+1][2 + lane]  = a1x;
            Cmb[2*qp+1][34 + lane] = a1y;
        }
    }
    __syncthreads();
    if (half == 0 && v0) {
        {   // query 0
            float mb = Cmb[2*qp][0], lb = Cmb[2*qp][1];
            float nm = fmaxf(m0, mb);
            float ca = __expf(m0 - nm), cb = __expf(mb - nm);
            float l  = l0 * ca + lb * cb;
            float ox = a0x * ca + Cmb[2*qp][2 + lane]  * cb;
            float oy = a0y * ca + Cmb[2*qp][34 + lane] * cb;
            float inv = 1.f / l;
            int iq = r + cq0 * p;
            float* orow = g_attn + (size_t)(b * T_ + iq) * D_ + h * HD_;
            orow[lane]      = ox * inv;
            orow[lane + 32] = oy * inv;
        }
        if (v1) {   // query 1
            float mb = Cmb[2*qp+1][0], lb = Cmb[2*qp+1][1];
            float nm = fmaxf(m1, mb);
            float ca = __expf(m1 - nm), cb = __expf(mb - nm);
            float l  = l1 * ca + lb * cb;
            float ox = a1x * ca + Cmb[2*qp+1][2 + lane]  * cb;
            float oy = a1y * ca + Cmb[2*qp+1][34 + lane] * cb;
            float inv = 1.f / l;
            int iq = r + cq1 * p;
            float* orow = g_attn + (size_t)(b * T_ + iq) * D_ + h * HD_;
            orow[lane]      = ox * inv;
            orow[lane + 32] = oy * inv;
        }
    }
}

// ---------------------------------------------------------------------------
extern "C" void kernel_launch(void* const* d_in, const int* in_sizes, int n_in,
                              void* d_out, int out_size)
{
    const float* x      = (const float*)d_in[0];
    const int*   periods= (const int*)  d_in[1];
    const float* w_qkv  = (const float*)d_in[2];
    const float* b_qkv  = (const float*)d_in[3];
    const float* w_out  = (const float*)d_in[4];
    const float* b_out  = (const float*)d_in[5];
    float*       out    = (float*)d_out;

    float* qkv_ptr = nullptr;
    float* attn_ptr = nullptr;
    cudaGetSymbolAddress((void**)&qkv_ptr, g_qkv);
    cudaGetSymbolAddress((void**)&attn_ptr, g_attn);

    {   // QKV projection: (4096 x 1536)
        dim3 grid(QKV3 / 128, NROW / 128);
        gemm_tf32_v4<<<grid, 256>>>(x, w_qkv, b_qkv, qkv_ptr, NROW, QKV3, D_);
    }
    {   // periodic-causal attention (residue classes, 16q tiles)
        // max needed grid.x over p<=63: p * ceil(ceil(2048/p)/16) <= 192
        dim3 grid(192, B_ * H_);
        attn_class_v2<<<grid, 512>>>(periods);
    }
    {   // output projection: (4096 x 512)
        dim3 grid(D_ / 128, NROW / 128);
        gemm_tf32_v4<<<grid, 256>>>(attn_ptr, w_out, b_out, out, NROW, D_, D_);
    }
}

// round 10
// speedup vs baseline: 1.4177x; 1.4177x over previous
#include <cuda_runtime.h>
#include <math.h>
#include <stdint.h>

#define B_   2
#define T_   2048
#define D_   512
#define H_   8
#define HD_  64
#define QKV3 (3 * D_)   // 1536
#define NROW (B_ * T_)  // 4096

__device__ float g_qkv[B_ * T_ * QKV3];
__device__ float g_attn[B_ * T_ * D_];

__device__ __forceinline__ uint32_t f2tf32(float x) {
    uint32_t u;
    asm("cvt.rna.tf32.f32 %0, %1;" : "=r"(u) : "f"(x));
    return u;
}
__device__ __forceinline__ void mma8(float c[4], const uint32_t a[4], uint2 b) {
    asm volatile(
        "mma.sync.aligned.m16n8k8.row.col.f32.tf32.tf32.f32 "
        "{%0,%1,%2,%3}, {%4,%5,%6,%7}, {%8,%9}, {%0,%1,%2,%3};"
        : "+f"(c[0]), "+f"(c[1]), "+f"(c[2]), "+f"(c[3])
        : "r"(a[0]), "r"(a[1]), "r"(a[2]), "r"(a[3]), "r"(b.x), "r"(b.y));
}

// ---------------------------------------------------------------------------
// TF32 GEMM v4 (round-7 proven): block 128x128, BK=16, 256 thr, 8 warps 64x32,
// double-buffered, pair-interleaved uint2 smem (LDS.64 frags).
// ---------------------------------------------------------------------------
#define MP  132
#define BSZ (8 * MP)

__global__ __launch_bounds__(256)
void gemm_tf32_v4(const float* __restrict__ A, const float* __restrict__ W,
                  const float* __restrict__ bias, float* __restrict__ C,
                  int N, int M, int K)
{
    __shared__ uint2 Asm[2][BSZ];
    __shared__ uint2 Wsm[2][BSZ];

    const int tid  = threadIdx.x;
    const int warp = tid >> 5;
    const int lane = tid & 31;
    const int g    = lane >> 2;
    const int t4   = lane & 3;

    const int n0 = blockIdx.y * 128;
    const int m0 = blockIdx.x * 128;
    const int r0 = (warp >> 2) * 64;
    const int c0 = (warp & 3) * 32;

    const int lrow = tid >> 1;
    const int lg2  = tid & 1;
    const float* Arow = A + (size_t)(n0 + lrow) * K + lg2 * 8;
    const float* Wrow = W + (size_t)(m0 + lrow) * K + lg2 * 8;

    float c[4][4][4];
#pragma unroll
    for (int mi = 0; mi < 4; mi++)
#pragma unroll
        for (int ni = 0; ni < 4; ni++)
#pragma unroll
            for (int q = 0; q < 4; q++) c[mi][ni][q] = 0.f;

    float4 av0, av1, wv0, wv1;

#define LD_TILE(koff)                              \
    av0 = *(const float4*)(Arow + (koff));         \
    av1 = *(const float4*)(Arow + (koff) + 4);     \
    wv0 = *(const float4*)(Wrow + (koff));         \
    wv1 = *(const float4*)(Wrow + (koff) + 4);

#define ST_TILE(buf)                                                  \
    {                                                                 \
        uint2* da = &Asm[(buf)][lg2 * 4 * MP + lrow];                 \
        da[0*MP] = make_uint2(f2tf32(av0.x), f2tf32(av1.x));          \
        da[1*MP] = make_uint2(f2tf32(av0.y), f2tf32(av1.y));          \
        da[2*MP] = make_uint2(f2tf32(av0.z), f2tf32(av1.z));          \
        da[3*MP] = make_uint2(f2tf32(av0.w), f2tf32(av1.w));          \
        uint2* dw = &Wsm[(buf)][lg2 * 4 * MP + lrow];                 \
        dw[0*MP] = make_uint2(f2tf32(wv0.x), f2tf32(wv1.x));          \
        dw[1*MP] = make_uint2(f2tf32(wv0.y), f2tf32(wv1.y));          \
        dw[2*MP] = make_uint2(f2tf32(wv0.z), f2tf32(wv1.z));          \
        dw[3*MP] = make_uint2(f2tf32(wv0.w), f2tf32(wv1.w));          \
    }

    LD_TILE(0);
    ST_TILE(0);
    __syncthreads();

    const int NT = K / 16;
    for (int it = 0; it < NT; it++) {
        if (it + 1 < NT) { LD_TILE((it + 1) * 16); }
        const int buf = it & 1;
#pragma unroll
        for (int g2 = 0; g2 < 2; g2++) {
            const uint2* ab = &Asm[buf][(g2 * 4 + t4) * MP];
            const uint2* wb = &Wsm[buf][(g2 * 4 + t4) * MP];
            uint2 bf[4];
#pragma unroll
            for (int ni = 0; ni < 4; ni++)
                bf[ni] = wb[c0 + ni * 8 + g];
#pragma unroll
            for (int mi = 0; mi < 4; mi++) {
                uint2 aL = ab[r0 + mi * 16 + g];
                uint2 aH = ab[r0 + mi * 16 + g + 8];
                uint32_t afr[4] = {aL.x, aH.x, aL.y, aH.y};
#pragma unroll
                for (int ni = 0; ni < 4; ni++)
                    mma8(c[mi][ni], afr, bf[ni]);
            }
        }
        if (it + 1 < NT) {
            __syncthreads();
            ST_TILE((it + 1) & 1);
            __syncthreads();
        }
    }

#pragma unroll
    for (int mi = 0; mi < 4; mi++) {
        int row_a = n0 + r0 + mi * 16 + g;
        int row_b = row_a + 8;
#pragma unroll
        for (int ni = 0; ni < 4; ni++) {
            int col = m0 + c0 + ni * 8 + 2 * t4;
            float bx = bias[col], by = bias[col + 1];
            *(float2*)(C + (size_t)row_a * M + col) =
                make_float2(c[mi][ni][0] + bx, c[mi][ni][1] + by);
            *(float2*)(C + (size_t)row_b * M + col) =
                make_float2(c[mi][ni][2] + bx, c[mi][ni][3] + by);
        }
    }
#undef LD_TILE
#undef ST_TILE
}

// ---------------------------------------------------------------------------
// MMA residue-class flash attention.
// Block = (bh, r, 64-query class tile). 256 thr = 8 warps = 4 m-tiles x 2
// n-halves. 64-key stages: K pair-interleaved tf32 (stride-36 uint2), V
// transposed dim-major same layout, P via smem (stride 76). Exact fp32
// online softmax, tf32 MMA for QK^T and PV.
// ---------------------------------------------------------------------------
#define KST 36   // uint2 per Ks2/Vt2 row
#define PST 76   // floats per Ps row
#define ATTN_SMEM (64*KST*8 + 64*KST*8 + 64*PST*4 + 128*4 + 128*4)

__global__ __launch_bounds__(256, 2)
void attn_mma(const int* __restrict__ periods)
{
    extern __shared__ char smc[];
    uint2* Ks2 = (uint2*)smc;
    uint2* Vt2 = Ks2 + 64 * KST;
    float* Ps  = (float*)(Vt2 + 64 * KST);
    float* Pmx = Ps + 64 * PST;
    float* Psm = Pmx + 128;

    const int bh = blockIdx.y;
    const int b  = bh >> 3;
    const int h  = bh & 7;
    int p = periods[bh];
    if (p < 1) p = 1;

    const int x    = blockIdx.x;
    const int r    = x % p;
    const int tile = x / p;
    const int c0   = tile * 64;
    const int L    = (T_ - 1 - r) / p + 1;
    if (c0 >= L) return;
    const int cmax = min(c0 + 63, L - 1);
    const int kmax = cmax;

    const int tid  = threadIdx.x;
    const int warp = tid >> 5;
    const int lane = tid & 31;
    const int g    = lane >> 2;
    const int t4   = lane & 3;
    const int mt   = warp >> 1;   // m-tile 0..3
    const int nh   = warp & 1;    // n-half 0..1

    const float* base = g_qkv + (size_t)b * T_ * QKV3;
    const float NEG = __int_as_float(0xff800000);   // -inf

    // zero-init K/V smem (stale rows must be finite)
    for (int i = tid; i < 64 * KST; i += 256) {
        Ks2[i] = make_uint2(0u, 0u);
        Vt2[i] = make_uint2(0u, 0u);
    }
    // stage scaled Q into Ps (rows > cmax -> 0)
    for (int u = tid; u < 64 * 16; u += 256) {
        int row = u >> 4, q4 = (u & 15) * 4;
        float4 v = make_float4(0.f, 0.f, 0.f, 0.f);
        int cq = c0 + row;
        if (cq <= cmax) {
            int iq = r + cq * p;
            v = *(const float4*)(base + (size_t)iq * QKV3 + h * HD_ + q4);
            v.x *= 0.125f; v.y *= 0.125f; v.z *= 0.125f; v.w *= 0.125f;
        }
        *(float4*)(Ps + row * PST + q4) = v;
    }
    __syncthreads();

    // Q fragments (held in registers for whole block)
    uint32_t qa[8][4];
    {
        const float* q0 = Ps + (mt * 16 + g) * PST;
        const float* q1 = q0 + 8 * PST;
#pragma unroll
        for (int s = 0; s < 8; s++) {
            qa[s][0] = f2tf32(q0[8 * s + t4]);
            qa[s][1] = f2tf32(q1[8 * s + t4]);
            qa[s][2] = f2tf32(q0[8 * s + 4 + t4]);
            qa[s][3] = f2tf32(q1[8 * s + 4 + t4]);
        }
    }

    float m0 = -1e30f, m1 = -1e30f, l0 = 0.f, l1 = 0.f;
    float o[4][4];
#pragma unroll
    for (int ns = 0; ns < 4; ns++)
#pragma unroll
        for (int j = 0; j < 4; j++) o[ns][j] = 0.f;

    const int cq0 = c0 + mt * 16 + g;
    const int cq1 = cq0 + 8;
    const int lim0 = (cq0 <= cmax) ? cq0 : -1;
    const int lim1 = (cq1 <= cmax) ? cq1 : -1;
    const int row0 = mt * 16 + g;
    const int row1 = row0 + 8;

    const int niter = kmax / 64 + 1;
    for (int t = 0; t < niter; t++) {
        __syncthreads();   // prior stage's K/V/P reads complete
        // ---- stage K (pair-interleaved) + V (transposed) ----
#pragma unroll
        for (int uu = 0; uu < 2; uu++) {
            int u = tid + 256 * uu;
            int key = u >> 3, s = u & 7;
            int ck = 64 * t + key;
            if (ck <= kmax) {
                int ik = r + ck * p;
                const float* kp_ = base + (size_t)ik * QKV3 + D_ + h * HD_ + 8 * s;
                float4 f0 = *(const float4*)kp_;
                float4 f1 = *(const float4*)(kp_ + 4);
                uint2* dst = Ks2 + key * KST + 4 * s;
                dst[0] = make_uint2(f2tf32(f0.x), f2tf32(f1.x));
                dst[1] = make_uint2(f2tf32(f0.y), f2tf32(f1.y));
                dst[2] = make_uint2(f2tf32(f0.z), f2tf32(f1.z));
                dst[3] = make_uint2(f2tf32(f0.w), f2tf32(f1.w));
                float4 v0 = *(const float4*)(kp_ + D_);
                float4 v1 = *(const float4*)(kp_ + D_ + 4);
                uint32_t* vt = (uint32_t*)Vt2;
                int wb = 2 * ((key >> 3) * 4 + (key & 3)) + ((key >> 2) & 1);
                vt[(8 * s + 0) * 2 * KST + wb] = f2tf32(v0.x);
                vt[(8 * s + 1) * 2 * KST + wb] = f2tf32(v0.y);
                vt[(8 * s + 2) * 2 * KST + wb] = f2tf32(v0.z);
                vt[(8 * s + 3) * 2 * KST + wb] = f2tf32(v0.w);
                vt[(8 * s + 4) * 2 * KST + wb] = f2tf32(v1.x);
                vt[(8 * s + 5) * 2 * KST + wb] = f2tf32(v1.y);
                vt[(8 * s + 6) * 2 * KST + wb] = f2tf32(v1.z);
                vt[(8 * s + 7) * 2 * KST + wb] = f2tf32(v1.w);
            }
        }
        __syncthreads();

        // ---- QK^T ----
        float sf[4][4];
#pragma unroll
        for (int ns = 0; ns < 4; ns++) {
#pragma unroll
            for (int j = 0; j < 4; j++) sf[ns][j] = 0.f;
            const uint2* kb = Ks2 + (nh * 32 + ns * 8 + g) * KST;
#pragma unroll
            for (int s = 0; s < 8; s++)
                mma8(sf[ns], qa[s], kb[4 * s + t4]);
        }
        // mask + row max partials
        float rx0 = NEG, rx1 = NEG;
#pragma unroll
        for (int ns = 0; ns < 4; ns++) {
            int ck = 64 * t + nh * 32 + ns * 8 + 2 * t4;
            sf[ns][0] = (ck     <= lim0) ? sf[ns][0] : NEG;
            sf[ns][1] = (ck + 1 <= lim0) ? sf[ns][1] : NEG;
            sf[ns][2] = (ck     <= lim1) ? sf[ns][2] : NEG;
            sf[ns][3] = (ck + 1 <= lim1) ? sf[ns][3] : NEG;
            rx0 = fmaxf(rx0, fmaxf(sf[ns][0], sf[ns][1]));
            rx1 = fmaxf(rx1, fmaxf(sf[ns][2], sf[ns][3]));
        }
        rx0 = fmaxf(rx0, __shfl_xor_sync(0xffffffffu, rx0, 1));
        rx0 = fmaxf(rx0, __shfl_xor_sync(0xffffffffu, rx0, 2));
        rx1 = fmaxf(rx1, __shfl_xor_sync(0xffffffffu, rx1, 1));
        rx1 = fmaxf(rx1, __shfl_xor_sync(0xffffffffu, rx1, 2));
        if (t4 == 0) {
            Pmx[nh * 64 + row0] = rx0;
            Pmx[nh * 64 + row1] = rx1;
        }
        __syncthreads();
        float nm0 = fmaxf(m0, fmaxf(Pmx[row0], Pmx[64 + row0]));
        float nm1 = fmaxf(m1, fmaxf(Pmx[row1], Pmx[64 + row1]));
        float co0 = __expf(m0 - nm0);
        float co1 = __expf(m1 - nm1);
        m0 = nm0; m1 = nm1;

        // exp (tf32-rounded), store P, partial sums
        float ps0 = 0.f, ps1 = 0.f;
#pragma unroll
        for (int ns = 0; ns < 4; ns++) {
            int col = nh * 32 + ns * 8 + 2 * t4;
            float p00 = __uint_as_float(f2tf32(__expf(sf[ns][0] - nm0)));
            float p01 = __uint_as_float(f2tf32(__expf(sf[ns][1] - nm0)));
            float p10 = __uint_as_float(f2tf32(__expf(sf[ns][2] - nm1)));
            float p11 = __uint_as_float(f2tf32(__expf(sf[ns][3] - nm1)));
            ps0 += p00 + p01;
            ps1 += p10 + p11;
            *(float2*)(Ps + row0 * PST + col) = make_float2(p00, p01);
            *(float2*)(Ps + row1 * PST + col) = make_float2(p10, p11);
        }
        ps0 += __shfl_xor_sync(0xffffffffu, ps0, 1);
        ps0 += __shfl_xor_sync(0xffffffffu, ps0, 2);
        ps1 += __shfl_xor_sync(0xffffffffu, ps1, 1);
        ps1 += __shfl_xor_sync(0xffffffffu, ps1, 2);
        if (t4 == 0) {
            Psm[nh * 64 + row0] = ps0;
            Psm[nh * 64 + row1] = ps1;
        }
        __syncthreads();
        l0 = l0 * co0 + Psm[row0] + Psm[64 + row0];
        l1 = l1 * co1 + Psm[row1] + Psm[64 + row1];

        // ---- rescale O, then PV ----
#pragma unroll
        for (int ns = 0; ns < 4; ns++) {
            o[ns][0] *= co0; o[ns][1] *= co0;
            o[ns][2] *= co1; o[ns][3] *= co1;
        }
        const float* pr0 = Ps + row0 * PST;
        const float* pr1 = Ps + row1 * PST;
#pragma unroll
        for (int s = 0; s < 8; s++) {
            uint32_t pa[4];
            pa[0] = __float_as_uint(pr0[8 * s + t4]);
            pa[1] = __float_as_uint(pr1[8 * s + t4]);
            pa[2] = __float_as_uint(pr0[8 * s + 4 + t4]);
            pa[3] = __float_as_uint(pr1[8 * s + 4 + t4]);
#pragma unroll
            for (int ns = 0; ns < 4; ns++) {
                uint2 vb = Vt2[(nh * 32 + ns * 8 + g) * KST + 4 * s + t4];
                mma8(o[ns], pa, vb);
            }
        }
    }

    // ---- epilogue ----
    float inv0 = 1.f / l0;
    float inv1 = 1.f / l1;
    if (cq0 <= cmax) {
        float* orow = g_attn + (size_t)(b * T_ + (r + cq0 * p)) * D_ + h * HD_;
#pragma unroll
        for (int ns = 0; ns < 4; ns++) {
            int col = nh * 32 + ns * 8 + 2 * t4;
            *(float2*)(orow + col) = make_float2(o[ns][0] * inv0, o[ns][1] * inv0);
        }
    }
    if (cq1 <= cmax) {
        float* orow = g_attn + (size_t)(b * T_ + (r + cq1 * p)) * D_ + h * HD_;
#pragma unroll
        for (int ns = 0; ns < 4; ns++) {
            int col = nh * 32 + ns * 8 + 2 * t4;
            *(float2*)(orow + col) = make_float2(o[ns][2] * inv1, o[ns][3] * inv1);
        }
    }
}

// ---------------------------------------------------------------------------
extern "C" void kernel_launch(void* const* d_in, const int* in_sizes, int n_in,
                              void* d_out, int out_size)
{
    const float* x      = (const float*)d_in[0];
    const int*   periods= (const int*)  d_in[1];
    const float* w_qkv  = (const float*)d_in[2];
    const float* b_qkv  = (const float*)d_in[3];
    const float* w_out  = (const float*)d_in[4];
    const float* b_out  = (const float*)d_in[5];
    float*       out    = (float*)d_out;

    float* qkv_ptr = nullptr;
    float* attn_ptr = nullptr;
    cudaGetSymbolAddress((void**)&qkv_ptr, g_qkv);
    cudaGetSymbolAddress((void**)&attn_ptr, g_attn);

    static bool attr_set = false;
    if (!attr_set) {
        cudaFuncSetAttribute(attn_mma,
                             cudaFuncAttributeMaxDynamicSharedMemorySize,
                             ATTN_SMEM);
        attr_set = true;
    }

    {   // QKV projection: (4096 x 1536)
        dim3 grid(QKV3 / 128, NROW / 128);
        gemm_tf32_v4<<<grid, 256>>>(x, w_qkv, b_qkv, qkv_ptr, NROW, QKV3, D_);
    }
    {   // periodic-causal attention (MMA residue classes)
        dim3 grid(64, B_ * H_);
        attn_mma<<<grid, 256, ATTN_SMEM>>>(periods);
    }
    {   // output projection: (4096 x 512)
        dim3 grid(D_ / 128, NROW / 128);
        gemm_tf32_v4<<<grid, 256>>>(attn_ptr, w_out, b_out, out, NROW, D_, D_);
    }
}

// round 12
// speedup vs baseline: 1.5393x; 1.0858x over previous
#include <cuda_runtime.h>
#include <math.h>
#include <stdint.h>

#define B_   2
#define T_   2048
#define D_   512
#define H_   8
#define HD_  64
#define QKV3 (3 * D_)   // 1536
#define NROW (B_ * T_)  // 4096

__device__ float    g_qkv[B_ * T_ * QKV3];
__device__ float    g_attn[B_ * T_ * D_];     // written tf32-rounded
__device__ uint32_t g_xt[NROW * D_];          // x as tf32 bits
__device__ uint32_t g_wqkvt[QKV3 * D_];       // w_qkv as tf32 bits
__device__ uint32_t g_woutt[D_ * D_];         // w_out as tf32 bits

__device__ __forceinline__ uint32_t f2tf32(float x) {
    uint32_t u;
    asm("cvt.rna.tf32.f32 %0, %1;" : "=r"(u) : "f"(x));
    return u;
}
__device__ __forceinline__ uint32_t smem_u32(const void* p) {
    uint32_t a;
    asm("{ .reg .u64 t; cvta.to.shared.u64 t, %1; cvt.u32.u64 %0, t; }"
        : "=r"(a) : "l"(p));
    return a;
}
__device__ __forceinline__ void mma8(float c[4], const uint32_t a[4], uint2 b) {
    asm volatile(
        "mma.sync.aligned.m16n8k8.row.col.f32.tf32.tf32.f32 "
        "{%0,%1,%2,%3}, {%4,%5,%6,%7}, {%8,%9}, {%0,%1,%2,%3};"
        : "+f"(c[0]), "+f"(c[1]), "+f"(c[2]), "+f"(c[3])
        : "r"(a[0]), "r"(a[1]), "r"(a[2]), "r"(a[3]), "r"(b.x), "r"(b.y));
}
__device__ __forceinline__ void ldsm4(uint32_t r[4], uint32_t addr) {
    asm volatile("ldmatrix.sync.aligned.m8n8.x4.shared.b16 {%0,%1,%2,%3}, [%4];"
                 : "=r"(r[0]), "=r"(r[1]), "=r"(r[2]), "=r"(r[3]) : "r"(addr));
}
__device__ __forceinline__ void cpa16(uint32_t dst, const void* src) {
    asm volatile("cp.async.cg.shared.global [%0], [%1], 16;" :: "r"(dst), "l"(src));
}
#define CP_COMMIT() asm volatile("cp.async.commit_group;" ::: "memory")
#define CP_WAIT(n)  asm volatile("cp.async.wait_group %0;" :: "n"(n) : "memory")

// ---------------------------------------------------------------------------
// Prepass: fp32 -> tf32 bits (float4 granular)
// ---------------------------------------------------------------------------
__global__ void cvt_tf32_kernel(const float* __restrict__ src,
                                uint32_t* __restrict__ dst, int n4)
{
    int i = blockIdx.x * blockDim.x + threadIdx.x;
    int stride = gridDim.x * blockDim.x;
    for (; i < n4; i += stride) {
        float4 v = ((const float4*)src)[i];
        uint4 o;
        o.x = f2tf32(v.x); o.y = f2tf32(v.y);
        o.z = f2tf32(v.z); o.w = f2tf32(v.w);
        ((uint4*)dst)[i] = o;
    }
}

// ---------------------------------------------------------------------------
// TF32 GEMM v5: inputs pre-converted tf32. Block 128x128, BK=16, 256 thr,
// 8 warps (2x4) of 64x32. cp.async staging into 80B-padded row-major smem,
// ldmatrix fragment loads, double-buffered.
// ---------------------------------------------------------------------------
#define RB   80                    // bytes per 16-elem row (64 + 16 pad)
#define TILE_B (128 * RB)          // 10240 bytes per matrix per buffer

__global__ __launch_bounds__(256)
void gemm_tf32_v5(const uint32_t* __restrict__ A, const uint32_t* __restrict__ W,
                  const float* __restrict__ bias, float* __restrict__ C,
                  int N, int M, int K)
{
    __shared__ char As[2][TILE_B];
    __shared__ char Ws[2][TILE_B];

    const int tid  = threadIdx.x;
    const int warp = tid >> 5;
    const int lane = tid & 31;
    const int g    = lane >> 2;
    const int t4   = lane & 3;

    const int n0 = blockIdx.y * 128;
    const int m0 = blockIdx.x * 128;
    const int r0 = (warp >> 2) * 64;   // 0 / 64
    const int c0 = (warp & 3) * 32;    // 0,32,64,96

    const uint32_t Abase = smem_u32(As);
    const uint32_t Wbase = smem_u32(Ws);

    // ldmatrix per-lane source row/chunk
    const int lmrow = (lane & 7) + (((lane >> 3) & 1) << 3);  // 0..15
    const int lmc   = (lane >> 4) * 16;                        // 0 / 16 bytes

    // cp.async assignments: 2 chunks per thread per matrix
    const int srow0 = tid >> 2, sc0 = (tid & 3) * 4;          // ids 0..255
    const int srow1 = srow0 + 64;                              // ids 256..511
    const uint32_t* Ag0 = A + (size_t)(n0 + srow0) * K + sc0;
    const uint32_t* Ag1 = A + (size_t)(n0 + srow1) * K + sc0;
    const uint32_t* Wg0 = W + (size_t)(m0 + srow0) * K + sc0;
    const uint32_t* Wg1 = W + (size_t)(m0 + srow1) * K + sc0;
    const uint32_t sA0 = srow0 * RB + sc0 * 4;
    const uint32_t sA1 = srow1 * RB + sc0 * 4;

    float c[4][4][4];
#pragma unroll
    for (int mi = 0; mi < 4; mi++)
#pragma unroll
        for (int ni = 0; ni < 4; ni++)
#pragma unroll
            for (int q = 0; q < 4; q++) c[mi][ni][q] = 0.f;

#define STAGE5(buf, koff)                                        \
    {                                                            \
        cpa16(Abase + (buf) * TILE_B + sA0, Ag0 + (koff));       \
        cpa16(Abase + (buf) * TILE_B + sA1, Ag1 + (koff));       \
        cpa16(Wbase + (buf) * TILE_B + sA0, Wg0 + (koff));       \
        cpa16(Wbase + (buf) * TILE_B + sA1, Wg1 + (koff));       \
        CP_COMMIT();                                             \
    }

    STAGE5(0, 0);

    const int NT = K / 16;
    for (int it = 0; it < NT; it++) {
        const int buf = it & 1;
        if (it + 1 < NT) { STAGE5(buf ^ 1, (it + 1) * 16); CP_WAIT(1); }
        else             { CP_WAIT(0); }
        __syncthreads();

        const uint32_t ab = Abase + buf * TILE_B + (r0 + lmrow) * RB + lmc;
        const uint32_t wb = Wbase + buf * TILE_B + (c0 + lmrow) * RB + lmc;
#pragma unroll
        for (int kh = 0; kh < 2; kh++) {
            uint32_t bfr[2][4];
            ldsm4(bfr[0], wb + kh * 32);
            ldsm4(bfr[1], wb + 16 * RB + kh * 32);
#pragma unroll
            for (int mi = 0; mi < 4; mi++) {
                uint32_t afr[4];
                ldsm4(afr, ab + mi * 16 * RB + kh * 32);
                mma8(c[mi][0], afr, make_uint2(bfr[0][0], bfr[0][2]));
                mma8(c[mi][1], afr, make_uint2(bfr[0][1], bfr[0][3]));
                mma8(c[mi][2], afr, make_uint2(bfr[1][0], bfr[1][2]));
                mma8(c[mi][3], afr, make_uint2(bfr[1][1], bfr[1][3]));
            }
        }
        __syncthreads();
    }

#pragma unroll
    for (int mi = 0; mi < 4; mi++) {
        int row_a = n0 + r0 + mi * 16 + g;
        int row_b = row_a + 8;
#pragma unroll
        for (int ni = 0; ni < 4; ni++) {
            int col = m0 + c0 + ni * 8 + 2 * t4;
            float bx = bias[col], by = bias[col + 1];
            *(float2*)(C + (size_t)row_a * M + col) =
                make_float2(c[mi][ni][0] + bx, c[mi][ni][1] + by);
            *(float2*)(C + (size_t)row_b * M + col) =
                make_float2(c[mi][ni][2] + bx, c[mi][ni][3] + by);
        }
    }
#undef STAGE5
}

// ---------------------------------------------------------------------------
// MMA residue-class flash attention (round-10 proven), epilogue writes
// tf32-rounded output for the v5 out-projection.
// ---------------------------------------------------------------------------
#define KST 36
#define PST 76
#define ATTN_SMEM (64*KST*8 + 64*KST*8 + 64*PST*4 + 128*4 + 128*4)

__global__ __launch_bounds__(256, 2)
void attn_mma(const int* __restrict__ periods)
{
    extern __shared__ char smc[];
    uint2* Ks2 = (uint2*)smc;
    uint2* Vt2 = Ks2 + 64 * KST;
    float* Ps  = (float*)(Vt2 + 64 * KST);
    float* Pmx = Ps + 64 * PST;
    float* Psm = Pmx + 128;

    const int bh = blockIdx.y;
    const int b  = bh >> 3;
    const int h  = bh & 7;
    int p = periods[bh];
    if (p < 1) p = 1;

    const int x    = blockIdx.x;
    const int r    = x % p;
    const int tile = x / p;
    const int c0   = tile * 64;
    const int L    = (T_ - 1 - r) / p + 1;
    if (c0 >= L) return;
    const int cmax = min(c0 + 63, L - 1);
    const int kmax = cmax;

    const int tid  = threadIdx.x;
    const int warp = tid >> 5;
    const int lane = tid & 31;
    const int g    = lane >> 2;
    const int t4   = lane & 3;
    const int mt   = warp >> 1;
    const int nh   = warp & 1;

    const float* base = g_qkv + (size_t)b * T_ * QKV3;
    const float NEG = __int_as_float(0xff800000);

    for (int i = tid; i < 64 * KST; i += 256) {
        Ks2[i] = make_uint2(0u, 0u);
        Vt2[i] = make_uint2(0u, 0u);
    }
    for (int u = tid; u < 64 * 16; u += 256) {
        int row = u >> 4, q4 = (u & 15) * 4;
        float4 v = make_float4(0.f, 0.f, 0.f, 0.f);
        int cq = c0 + row;
        if (cq <= cmax) {
            int iq = r + cq * p;
            v = *(const float4*)(base + (size_t)iq * QKV3 + h * HD_ + q4);
            v.x *= 0.125f; v.y *= 0.125f; v.z *= 0.125f; v.w *= 0.125f;
        }
        *(float4*)(Ps + row * PST + q4) = v;
    }
    __syncthreads();

    uint32_t qa[8][4];
    {
        const float* q0 = Ps + (mt * 16 + g) * PST;
        const float* q1 = q0 + 8 * PST;
#pragma unroll
        for (int s = 0; s < 8; s++) {
            qa[s][0] = f2tf32(q0[8 * s + t4]);
            qa[s][1] = f2tf32(q1[8 * s + t4]);
            qa[s][2] = f2tf32(q0[8 * s + 4 + t4]);
            qa[s][3] = f2tf32(q1[8 * s + 4 + t4]);
        }
    }

    float m0 = -1e30f, m1 = -1e30f, l0 = 0.f, l1 = 0.f;
    float o[4][4];
#pragma unroll
    for (int ns = 0; ns < 4; ns++)
#pragma unroll
        for (int j = 0; j < 4; j++) o[ns][j] = 0.f;

    const int cq0 = c0 + mt * 16 + g;
    const int cq1 = cq0 + 8;
    const int lim0 = (cq0 <= cmax) ? cq0 : -1;
    const int lim1 = (cq1 <= cmax) ? cq1 : -1;
    const int row0 = mt * 16 + g;
    const int row1 = row0 + 8;

    const int niter = kmax / 64 + 1;
    for (int t = 0; t < niter; t++) {
        __syncthreads();
#pragma unroll
        for (int uu = 0; uu < 2; uu++) {
            int u = tid + 256 * uu;
            int key = u >> 3, s = u & 7;
            int ck = 64 * t + key;
            if (ck <= kmax) {
                int ik = r + ck * p;
                const float* kp_ = base + (size_t)ik * QKV3 + D_ + h * HD_ + 8 * s;
                float4 f0 = *(const float4*)kp_;
                float4 f1 = *(const float4*)(kp_ + 4);
                uint2* dst = Ks2 + key * KST + 4 * s;
                dst[0] = make_uint2(f2tf32(f0.x), f2tf32(f1.x));
                dst[1] = make_uint2(f2tf32(f0.y), f2tf32(f1.y));
                dst[2] = make_uint2(f2tf32(f0.z), f2tf32(f1.z));
                dst[3] = make_uint2(f2tf32(f0.w), f2tf32(f1.w));
                float4 v0 = *(const float4*)(kp_ + D_);
                float4 v1 = *(const float4*)(kp_ + D_ + 4);
                uint32_t* vt = (uint32_t*)Vt2;
                int wb = 2 * ((key >> 3) * 4 + (key & 3)) + ((key >> 2) & 1);
                vt[(8 * s + 0) * 2 * KST + wb] = f2tf32(v0.x);
                vt[(8 * s + 1) * 2 * KST + wb] = f2tf32(v0.y);
                vt[(8 * s + 2) * 2 * KST + wb] = f2tf32(v0.z);
                vt[(8 * s + 3) * 2 * KST + wb] = f2tf32(v0.w);
                vt[(8 * s + 4) * 2 * KST + wb] = f2tf32(v1.x);
                vt[(8 * s + 5) * 2 * KST + wb] = f2tf32(v1.y);
                vt[(8 * s + 6) * 2 * KST + wb] = f2tf32(v1.z);
                vt[(8 * s + 7) * 2 * KST + wb] = f2tf32(v1.w);
            }
        }
        __syncthreads();

        float sf[4][4];
#pragma unroll
        for (int ns = 0; ns < 4; ns++) {
#pragma unroll
            for (int j = 0; j < 4; j++) sf[ns][j] = 0.f;
            const uint2* kb = Ks2 + (nh * 32 + ns * 8 + g) * KST;
#pragma unroll
            for (int s = 0; s < 8; s++)
                mma8(sf[ns], qa[s], kb[4 * s + t4]);
        }
        float rx0 = NEG, rx1 = NEG;
#pragma unroll
        for (int ns = 0; ns < 4; ns++) {
            int ck = 64 * t + nh * 32 + ns * 8 + 2 * t4;
            sf[ns][0] = (ck     <= lim0) ? sf[ns][0] : NEG;
            sf[ns][1] = (ck + 1 <= lim0) ? sf[ns][1] : NEG;
            sf[ns][2] = (ck     <= lim1) ? sf[ns][2] : NEG;
            sf[ns][3] = (ck + 1 <= lim1) ? sf[ns][3] : NEG;
            rx0 = fmaxf(rx0, fmaxf(sf[ns][0], sf[ns][1]));
            rx1 = fmaxf(rx1, fmaxf(sf[ns][2], sf[ns][3]));
        }
        rx0 = fmaxf(rx0, __shfl_xor_sync(0xffffffffu, rx0, 1));
        rx0 = fmaxf(rx0, __shfl_xor_sync(0xffffffffu, rx0, 2));
        rx1 = fmaxf(rx1, __shfl_xor_sync(0xffffffffu, rx1, 1));
        rx1 = fmaxf(rx1, __shfl_xor_sync(0xffffffffu, rx1, 2));
        if (t4 == 0) {
            Pmx[nh * 64 + row0] = rx0;
            Pmx[nh * 64 + row1] = rx1;
        }
        __syncthreads();
        float nm0 = fmaxf(m0, fmaxf(Pmx[row0], Pmx[64 + row0]));
        float nm1 = fmaxf(m1, fmaxf(Pmx[row1], Pmx[64 + row1]));
        float co0 = __expf(m0 - nm0);
        float co1 = __expf(m1 - nm1);
        m0 = nm0; m1 = nm1;

        float ps0 = 0.f, ps1 = 0.f;
#pragma unroll
        for (int ns = 0; ns < 4; ns++) {
            int col = nh * 32 + ns * 8 + 2 * t4;
            float p00 = __uint_as_float(f2tf32(__expf(sf[ns][0] - nm0)));
            float p01 = __uint_as_float(f2tf32(__expf(sf[ns][1] - nm0)));
            float p10 = __uint_as_float(f2tf32(__expf(sf[ns][2] - nm1)));
            float p11 = __uint_as_float(f2tf32(__expf(sf[ns][3] - nm1)));
            ps0 += p00 + p01;
            ps1 += p10 + p11;
            *(float2*)(Ps + row0 * PST + col) = make_float2(p00, p01);
            *(float2*)(Ps + row1 * PST + col) = make_float2(p10, p11);
        }
        ps0 += __shfl_xor_sync(0xffffffffu, ps0, 1);
        ps0 += __shfl_xor_sync(0xffffffffu, ps0, 2);
        ps1 += __shfl_xor_sync(0xffffffffu, ps1, 1);
        ps1 += __shfl_xor_sync(0xffffffffu, ps1, 2);
        if (t4 == 0) {
            Psm[nh * 64 + row0] = ps0;
            Psm[nh * 64 + row1] = ps1;
        }
        __syncthreads();
        l0 = l0 * co0 + Psm[row0] + Psm[64 + row0];
        l1 = l1 * co1 + Psm[row1] + Psm[64 + row1];

#pragma unroll
        for (int ns = 0; ns < 4; ns++) {
            o[ns][0] *= co0; o[ns][1] *= co0;
            o[ns][2] *= co1; o[ns][3] *= co1;
        }
        const float* pr0 = Ps + row0 * PST;
        const float* pr1 = Ps + row1 * PST;
#pragma unroll
        for (int s = 0; s < 8; s++) {
            uint32_t pa[4];
            pa[0] = __float_as_uint(pr0[8 * s + t4]);
            pa[1] = __float_as_uint(pr1[8 * s + t4]);
            pa[2] = __float_as_uint(pr0[8 * s + 4 + t4]);
            pa[3] = __float_as_uint(pr1[8 * s + 4 + t4]);
#pragma unroll
            for (int ns = 0; ns < 4; ns++) {
                uint2 vb = Vt2[(nh * 32 + ns * 8 + g) * KST + 4 * s + t4];
                mma8(o[ns], pa, vb);
            }
        }
    }

    float inv0 = 1.f / l0;
    float inv1 = 1.f / l1;
    if (cq0 <= cmax) {
        float* orow = g_attn + (size_t)(b * T_ + (r + cq0 * p)) * D_ + h * HD_;
#pragma unroll
        for (int ns = 0; ns < 4; ns++) {
            int col = nh * 32 + ns * 8 + 2 * t4;
            *(uint2*)(orow + col) = make_uint2(f2tf32(o[ns][0] * inv0),
                                               f2tf32(o[ns][1] * inv0));
        }
    }
    if (cq1 <= cmax) {
        float* orow = g_attn + (size_t)(b * T_ + (r + cq1 * p)) * D_ + h * HD_;
#pragma unroll
        for (int ns = 0; ns < 4; ns++) {
            int col = nh * 32 + ns * 8 + 2 * t4;
            *(uint2*)(orow + col) = make_uint2(f2tf32(o[ns][2] * inv1),
                                               f2tf32(o[ns][3] * inv1));
        }
    }
}

// ---------------------------------------------------------------------------
extern "C" void kernel_launch(void* const* d_in, const int* in_sizes, int n_in,
                              void* d_out, int out_size)
{
    const float* x      = (const float*)d_in[0];
    const int*   periods= (const int*)  d_in[1];
    const float* w_qkv  = (const float*)d_in[2];
    const float* b_qkv  = (const float*)d_in[3];
    const float* w_out  = (const float*)d_in[4];
    const float* b_out  = (const float*)d_in[5];
    float*       out    = (float*)d_out;

    float *qkv_ptr, *attn_ptr;
    uint32_t *xt, *wqt, *wot;
    cudaGetSymbolAddress((void**)&qkv_ptr, g_qkv);
    cudaGetSymbolAddress((void**)&attn_ptr, g_attn);
    cudaGetSymbolAddress((void**)&xt,  g_xt);
    cudaGetSymbolAddress((void**)&wqt, g_wqkvt);
    cudaGetSymbolAddress((void**)&wot, g_woutt);

    static bool attr_set = false;
    if (!attr_set) {
        cudaFuncSetAttribute(attn_mma,
                             cudaFuncAttributeMaxDynamicSharedMemorySize,
                             ATTN_SMEM);
        attr_set = true;
    }

    // 0) prepass: convert x / w_qkv / w_out to tf32
    cvt_tf32_kernel<<<512, 256>>>(x,     xt,  NROW * D_ / 4);
    cvt_tf32_kernel<<<512, 256>>>(w_qkv, wqt, QKV3 * D_ / 4);
    cvt_tf32_kernel<<<512, 256>>>(w_out, wot, D_ * D_ / 4);

    {   // 1) QKV projection
        dim3 grid(QKV3 / 128, NROW / 128);
        gemm_tf32_v5<<<grid, 256>>>(xt, wqt, b_qkv, qkv_ptr, NROW, QKV3, D_);
    }
    {   // 2) periodic-causal attention
        dim3 grid(64, B_ * H_);
        attn_mma<<<grid, 256, ATTN_SMEM>>>(periods);
    }
    {   // 3) output projection (g_attn already tf32-rounded)
        dim3 grid(D_ / 128, NROW / 128);
        gemm_tf32_v5<<<grid, 256>>>((const uint32_t*)attn_ptr, wot, b_out, out,
                                    NROW, D_, D_);
    }
}

// round 13
// speedup vs baseline: 1.7442x; 1.1331x over previous
#include <cuda_runtime.h>
#include <math.h>
#include <stdint.h>

#define B_   2
#define T_   2048
#define D_   512
#define H_   8
#define HD_  64
#define QKV3 (3 * D_)   // 1536
#define NROW (B_ * T_)  // 4096

__device__ float    g_qkv[B_ * T_ * QKV3];
__device__ float    g_attn[B_ * T_ * D_];     // written tf32-rounded
__device__ uint32_t g_xt[NROW * D_];
__device__ uint32_t g_wqkvt[QKV3 * D_];
__device__ uint32_t g_woutt[D_ * D_];

__device__ __forceinline__ uint32_t f2tf32(float x) {
    uint32_t u;
    asm("cvt.rna.tf32.f32 %0, %1;" : "=r"(u) : "f"(x));
    return u;
}
__device__ __forceinline__ uint32_t smem_u32(const void* p) {
    uint32_t a;
    asm("{ .reg .u64 t; cvta.to.shared.u64 t, %1; cvt.u32.u64 %0, t; }"
        : "=r"(a) : "l"(p));
    return a;
}
__device__ __forceinline__ void mma8(float c[4], const uint32_t a[4], uint2 b) {
    asm volatile(
        "mma.sync.aligned.m16n8k8.row.col.f32.tf32.tf32.f32 "
        "{%0,%1,%2,%3}, {%4,%5,%6,%7}, {%8,%9}, {%0,%1,%2,%3};"
        : "+f"(c[0]), "+f"(c[1]), "+f"(c[2]), "+f"(c[3])
        : "r"(a[0]), "r"(a[1]), "r"(a[2]), "r"(a[3]), "r"(b.x), "r"(b.y));
}
__device__ __forceinline__ void ldsm4(uint32_t r[4], uint32_t addr) {
    asm volatile("ldmatrix.sync.aligned.m8n8.x4.shared.b16 {%0,%1,%2,%3}, [%4];"
                 : "=r"(r[0]), "=r"(r[1]), "=r"(r[2]), "=r"(r[3]) : "r"(addr));
}
__device__ __forceinline__ void cpa16(uint32_t dst, const void* src) {
    asm volatile("cp.async.cg.shared.global [%0], [%1], 16;" :: "r"(dst), "l"(src));
}
#define CP_COMMIT() asm volatile("cp.async.commit_group;" ::: "memory")
#define CP_WAIT(n)  asm volatile("cp.async.wait_group %0;" :: "n"(n) : "memory")

// ---------------------------------------------------------------------------
// Fused prepass: x / w_qkv / w_out -> tf32 bits, one launch
// ---------------------------------------------------------------------------
#define N4X (NROW * D_ / 4)
#define N4Q (QKV3 * D_ / 4)
#define N4O (D_ * D_ / 4)

__global__ void cvt_all_kernel(const float* __restrict__ x,
                               const float* __restrict__ wq,
                               const float* __restrict__ wo)
{
    int i = blockIdx.x * blockDim.x + threadIdx.x;
    int stride = gridDim.x * blockDim.x;
    const int ntot = N4X + N4Q + N4O;
    for (; i < ntot; i += stride) {
        const float4* src;
        uint4* dst;
        if (i < N4X)            { src = (const float4*)x  + i;
                                  dst = (uint4*)g_xt + i; }
        else if (i < N4X + N4Q) { src = (const float4*)wq + (i - N4X);
                                  dst = (uint4*)g_wqkvt + (i - N4X); }
        else                    { src = (const float4*)wo + (i - N4X - N4Q);
                                  dst = (uint4*)g_woutt + (i - N4X - N4Q); }
        float4 v = *src;
        *dst = make_uint4(f2tf32(v.x), f2tf32(v.y), f2tf32(v.z), f2tf32(v.w));
    }
}

// ---------------------------------------------------------------------------
// TF32 GEMM v6: 4-stage cp.async ring. Block 128x128, BK=16, 256 thr,
// 8 warps (2x4) of 64x32, ldmatrix frags, pre-converted tf32 inputs.
// ---------------------------------------------------------------------------
#define RB   80
#define TILE_B (128 * RB)          // 10240 B per matrix per stage
#define NSTG 4
#define G6_SMEM (NSTG * 2 * TILE_B)   // 81920 B

__global__ __launch_bounds__(256)
void gemm_tf32_v6(const uint32_t* __restrict__ A, const uint32_t* __restrict__ W,
                  const float* __restrict__ bias, float* __restrict__ C,
                  int N, int M, int K)
{
    extern __shared__ char sm6[];
    const uint32_t Abase = smem_u32(sm6);
    const uint32_t Wbase = Abase + NSTG * TILE_B;

    const int tid  = threadIdx.x;
    const int warp = tid >> 5;
    const int lane = tid & 31;
    const int g    = lane >> 2;
    const int t4   = lane & 3;

    const int n0 = blockIdx.y * 128;
    const int m0 = blockIdx.x * 128;
    const int r0 = (warp >> 2) * 64;
    const int c0 = (warp & 3) * 32;

    const int lmrow = (lane & 7) + (((lane >> 3) & 1) << 3);
    const int lmc   = (lane >> 4) * 16;

    const int srow0 = tid >> 2, sc0 = (tid & 3) * 4;
    const int srow1 = srow0 + 64;
    const uint32_t* Ag0 = A + (size_t)(n0 + srow0) * K + sc0;
    const uint32_t* Ag1 = A + (size_t)(n0 + srow1) * K + sc0;
    const uint32_t* Wg0 = W + (size_t)(m0 + srow0) * K + sc0;
    const uint32_t* Wg1 = W + (size_t)(m0 + srow1) * K + sc0;
    const uint32_t sA0 = srow0 * RB + sc0 * 4;
    const uint32_t sA1 = srow1 * RB + sc0 * 4;

    float c[4][4][4];
#pragma unroll
    for (int mi = 0; mi < 4; mi++)
#pragma unroll
        for (int ni = 0; ni < 4; ni++)
#pragma unroll
            for (int q = 0; q < 4; q++) c[mi][ni][q] = 0.f;

#define STAGE6(buf, koff)                                        \
    {                                                            \
        cpa16(Abase + (buf) * TILE_B + sA0, Ag0 + (koff));       \
        cpa16(Abase + (buf) * TILE_B + sA1, Ag1 + (koff));       \
        cpa16(Wbase + (buf) * TILE_B + sA0, Wg0 + (koff));       \
        cpa16(Wbase + (buf) * TILE_B + sA1, Wg1 + (koff));       \
    }

    const int NT = K / 16;   // >= 32 for all our calls
    STAGE6(0, 0);  CP_COMMIT();
    STAGE6(1, 16); CP_COMMIT();
    STAGE6(2, 32); CP_COMMIT();

    for (int it = 0; it < NT; it++) {
        CP_WAIT(2);
        __syncthreads();
        // issue prefetch for stage it+3 (buffer reuse is safe: all warps have
        // finished compute of it-1 after the sync above)
        if (it + 3 < NT) { STAGE6((it + 3) & 3, (it + 3) * 16); }
        CP_COMMIT();   // one group per iteration (possibly empty)

        const int buf = it & 3;
        const uint32_t ab = Abase + buf * TILE_B + (r0 + lmrow) * RB + lmc;
        const uint32_t wb = Wbase + buf * TILE_B + (c0 + lmrow) * RB + lmc;
#pragma unroll
        for (int kh = 0; kh < 2; kh++) {
            uint32_t bfr[2][4];
            ldsm4(bfr[0], wb + kh * 32);
            ldsm4(bfr[1], wb + 16 * RB + kh * 32);
#pragma unroll
            for (int mi = 0; mi < 4; mi++) {
                uint32_t afr[4];
                ldsm4(afr, ab + mi * 16 * RB + kh * 32);
                mma8(c[mi][0], afr, make_uint2(bfr[0][0], bfr[0][2]));
                mma8(c[mi][1], afr, make_uint2(bfr[0][1], bfr[0][3]));
                mma8(c[mi][2], afr, make_uint2(bfr[1][0], bfr[1][2]));
                mma8(c[mi][3], afr, make_uint2(bfr[1][1], bfr[1][3]));
            }
        }
    }
    __syncthreads();

#pragma unroll
    for (int mi = 0; mi < 4; mi++) {
        int row_a = n0 + r0 + mi * 16 + g;
        int row_b = row_a + 8;
#pragma unroll
        for (int ni = 0; ni < 4; ni++) {
            int col = m0 + c0 + ni * 8 + 2 * t4;
            float bx = bias[col], by = bias[col + 1];
            *(float2*)(C + (size_t)row_a * M + col) =
                make_float2(c[mi][ni][0] + bx, c[mi][ni][1] + by);
            *(float2*)(C + (size_t)row_b * M + col) =
                make_float2(c[mi][ni][2] + bx, c[mi][ni][3] + by);
        }
    }
#undef STAGE6
}

// ---------------------------------------------------------------------------
// MMA residue-class flash attention (round-10 proven; tf32-rounded epilogue).
// ---------------------------------------------------------------------------
#define KST 36
#define PST 76
#define ATTN_SMEM (64*KST*8 + 64*KST*8 + 64*PST*4 + 128*4 + 128*4)

__global__ __launch_bounds__(256, 2)
void attn_mma(const int* __restrict__ periods)
{
    extern __shared__ char smc[];
    uint2* Ks2 = (uint2*)smc;
    uint2* Vt2 = Ks2 + 64 * KST;
    float* Ps  = (float*)(Vt2 + 64 * KST);
    float* Pmx = Ps + 64 * PST;
    float* Psm = Pmx + 128;

    const int bh = blockIdx.y;
    const int b  = bh >> 3;
    const int h  = bh & 7;
    int p = periods[bh];
    if (p < 1) p = 1;

    const int x    = blockIdx.x;
    const int r    = x % p;
    const int tile = x / p;
    const int c0   = tile * 64;
    const int L    = (T_ - 1 - r) / p + 1;
    if (c0 >= L) return;
    const int cmax = min(c0 + 63, L - 1);
    const int kmax = cmax;

    const int tid  = threadIdx.x;
    const int warp = tid >> 5;
    const int lane = tid & 31;
    const int g    = lane >> 2;
    const int t4   = lane & 3;
    const int mt   = warp >> 1;
    const int nh   = warp & 1;

    const float* base = g_qkv + (size_t)b * T_ * QKV3;
    const float NEG = __int_as_float(0xff800000);

    for (int i = tid; i < 64 * KST; i += 256) {
        Ks2[i] = make_uint2(0u, 0u);
        Vt2[i] = make_uint2(0u, 0u);
    }
    for (int u = tid; u < 64 * 16; u += 256) {
        int row = u >> 4, q4 = (u & 15) * 4;
        float4 v = make_float4(0.f, 0.f, 0.f, 0.f);
        int cq = c0 + row;
        if (cq <= cmax) {
            int iq = r + cq * p;
            v = *(const float4*)(base + (size_t)iq * QKV3 + h * HD_ + q4);
            v.x *= 0.125f; v.y *= 0.125f; v.z *= 0.125f; v.w *= 0.125f;
        }
        *(float4*)(Ps + row * PST + q4) = v;
    }
    __syncthreads();

    uint32_t qa[8][4];
    {
        const float* q0 = Ps + (mt * 16 + g) * PST;
        const float* q1 = q0 + 8 * PST;
#pragma unroll
        for (int s = 0; s < 8; s++) {
            qa[s][0] = f2tf32(q0[8 * s + t4]);
            qa[s][1] = f2tf32(q1[8 * s + t4]);
            qa[s][2] = f2tf32(q0[8 * s + 4 + t4]);
            qa[s][3] = f2tf32(q1[8 * s + 4 + t4]);
        }
    }

    float m0 = -1e30f, m1 = -1e30f, l0 = 0.f, l1 = 0.f;
    float o[4][4];
#pragma unroll
    for (int ns = 0; ns < 4; ns++)
#pragma unroll
        for (int j = 0; j < 4; j++) o[ns][j] = 0.f;

    const int cq0 = c0 + mt * 16 + g;
    const int cq1 = cq0 + 8;
    const int lim0 = (cq0 <= cmax) ? cq0 : -1;
    const int lim1 = (cq1 <= cmax) ? cq1 : -1;
    const int row0 = mt * 16 + g;
    const int row1 = row0 + 8;

    const int niter = kmax / 64 + 1;
    for (int t = 0; t < niter; t++) {
        __syncthreads();
#pragma unroll
        for (int uu = 0; uu < 2; uu++) {
            int u = tid + 256 * uu;
            int key = u >> 3, s = u & 7;
            int ck = 64 * t + key;
            if (ck <= kmax) {
                int ik = r + ck * p;
                const float* kp_ = base + (size_t)ik * QKV3 + D_ + h * HD_ + 8 * s;
                float4 f0 = *(const float4*)kp_;
                float4 f1 = *(const float4*)(kp_ + 4);
                uint2* dst = Ks2 + key * KST + 4 * s;
                dst[0] = make_uint2(f2tf32(f0.x), f2tf32(f1.x));
                dst[1] = make_uint2(f2tf32(f0.y), f2tf32(f1.y));
                dst[2] = make_uint2(f2tf32(f0.z), f2tf32(f1.z));
                dst[3] = make_uint2(f2tf32(f0.w), f2tf32(f1.w));
                float4 v0 = *(const float4*)(kp_ + D_);
                float4 v1 = *(const float4*)(kp_ + D_ + 4);
                uint32_t* vt = (uint32_t*)Vt2;
                int wb = 2 * ((key >> 3) * 4 + (key & 3)) + ((key >> 2) & 1);
                vt[(8 * s + 0) * 2 * KST + wb] = f2tf32(v0.x);
                vt[(8 * s + 1) * 2 * KST + wb] = f2tf32(v0.y);
                vt[(8 * s + 2) * 2 * KST + wb] = f2tf32(v0.z);
                vt[(8 * s + 3) * 2 * KST + wb] = f2tf32(v0.w);
                vt[(8 * s + 4) * 2 * KST + wb] = f2tf32(v1.x);
                vt[(8 * s + 5) * 2 * KST + wb] = f2tf32(v1.y);
                vt[(8 * s + 6) * 2 * KST + wb] = f2tf32(v1.z);
                vt[(8 * s + 7) * 2 * KST + wb] = f2tf32(v1.w);
            }
        }
        __syncthreads();

        float sf[4][4];
#pragma unroll
        for (int ns = 0; ns < 4; ns++) {
#pragma unroll
            for (int j = 0; j < 4; j++) sf[ns][j] = 0.f;
            const uint2* kb = Ks2 + (nh * 32 + ns * 8 + g) * KST;
#pragma unroll
            for (int s = 0; s < 8; s++)
                mma8(sf[ns], qa[s], kb[4 * s + t4]);
        }
        float rx0 = NEG, rx1 = NEG;
#pragma unroll
        for (int ns = 0; ns < 4; ns++) {
            int ck = 64 * t + nh * 32 + ns * 8 + 2 * t4;
            sf[ns][0] = (ck     <= lim0) ? sf[ns][0] : NEG;
            sf[ns][1] = (ck + 1 <= lim0) ? sf[ns][1] : NEG;
            sf[ns][2] = (ck     <= lim1) ? sf[ns][2] : NEG;
            sf[ns][3] = (ck + 1 <= lim1) ? sf[ns][3] : NEG;
            rx0 = fmaxf(rx0, fmaxf(sf[ns][0], sf[ns][1]));
            rx1 = fmaxf(rx1, fmaxf(sf[ns][2], sf[ns][3]));
        }
        rx0 = fmaxf(rx0, __shfl_xor_sync(0xffffffffu, rx0, 1));
        rx0 = fmaxf(rx0, __shfl_xor_sync(0xffffffffu, rx0, 2));
        rx1 = fmaxf(rx1, __shfl_xor_sync(0xffffffffu, rx1, 1));
        rx1 = fmaxf(rx1, __shfl_xor_sync(0xffffffffu, rx1, 2));
        if (t4 == 0) {
            Pmx[nh * 64 + row0] = rx0;
            Pmx[nh * 64 + row1] = rx1;
        }
        __syncthreads();
        float nm0 = fmaxf(m0, fmaxf(Pmx[row0], Pmx[64 + row0]));
        float nm1 = fmaxf(m1, fmaxf(Pmx[row1], Pmx[64 + row1]));
        float co0 = __expf(m0 - nm0);
        float co1 = __expf(m1 - nm1);
        m0 = nm0; m1 = nm1;

        float ps0 = 0.f, ps1 = 0.f;
#pragma unroll
        for (int ns = 0; ns < 4; ns++) {
            int col = nh * 32 + ns * 8 + 2 * t4;
            float p00 = __uint_as_float(f2tf32(__expf(sf[ns][0] - nm0)));
            float p01 = __uint_as_float(f2tf32(__expf(sf[ns][1] - nm0)));
            float p10 = __uint_as_float(f2tf32(__expf(sf[ns][2] - nm1)));
            float p11 = __uint_as_float(f2tf32(__expf(sf[ns][3] - nm1)));
            ps0 += p00 + p01;
            ps1 += p10 + p11;
            *(float2*)(Ps + row0 * PST + col) = make_float2(p00, p01);
            *(float2*)(Ps + row1 * PST + col) = make_float2(p10, p11);
        }
        ps0 += __shfl_xor_sync(0xffffffffu, ps0, 1);
        ps0 += __shfl_xor_sync(0xffffffffu, ps0, 2);
        ps1 += __shfl_xor_sync(0xffffffffu, ps1, 1);
        ps1 += __shfl_xor_sync(0xffffffffu, ps1, 2);
        if (t4 == 0) {
            Psm[nh * 64 + row0] = ps0;
            Psm[nh * 64 + row1] = ps1;
        }
        __syncthreads();
        l0 = l0 * co0 + Psm[row0] + Psm[64 + row0];
        l1 = l1 * co1 + Psm[row1] + Psm[64 + row1];

#pragma unroll
        for (int ns = 0; ns < 4; ns++) {
            o[ns][0] *= co0; o[ns][1] *= co0;
            o[ns][2] *= co1; o[ns][3] *= co1;
        }
        const float* pr0 = Ps + row0 * PST;
        const float* pr1 = Ps + row1 * PST;
#pragma unroll
        for (int s = 0; s < 8; s++) {
            uint32_t pa[4];
            pa[0] = __float_as_uint(pr0[8 * s + t4]);
            pa[1] = __float_as_uint(pr1[8 * s + t4]);
            pa[2] = __float_as_uint(pr0[8 * s + 4 + t4]);
            pa[3] = __float_as_uint(pr1[8 * s + 4 + t4]);
#pragma unroll
            for (int ns = 0; ns < 4; ns++) {
                uint2 vb = Vt2[(nh * 32 + ns * 8 + g) * KST + 4 * s + t4];
                mma8(o[ns], pa, vb);
            }
        }
    }

    float inv0 = 1.f / l0;
    float inv1 = 1.f / l1;
    if (cq0 <= cmax) {
        float* orow = g_attn + (size_t)(b * T_ + (r + cq0 * p)) * D_ + h * HD_;
#pragma unroll
        for (int ns = 0; ns < 4; ns++) {
            int col = nh * 32 + ns * 8 + 2 * t4;
            *(uint2*)(orow + col) = make_uint2(f2tf32(o[ns][0] * inv0),
                                               f2tf32(o[ns][1] * inv0));
        }
    }
    if (cq1 <= cmax) {
        float* orow = g_attn + (size_t)(b * T_ + (r + cq1 * p)) * D_ + h * HD_;
#pragma unroll
        for (int ns = 0; ns < 4; ns++) {
            int col = nh * 32 + ns * 8 + 2 * t4;
            *(uint2*)(orow + col) = make_uint2(f2tf32(o[ns][2] * inv1),
                                               f2tf32(o[ns][3] * inv1));
        }
    }
}

// ---------------------------------------------------------------------------
extern "C" void kernel_launch(void* const* d_in, const int* in_sizes, int n_in,
                              void* d_out, int out_size)
{
    const float* x      = (const float*)d_in[0];
    const int*   periods= (const int*)  d_in[1];
    const float* w_qkv  = (const float*)d_in[2];
    const float* b_qkv  = (const float*)d_in[3];
    const float* w_out  = (const float*)d_in[4];
    const float* b_out  = (const float*)d_in[5];
    float*       out    = (float*)d_out;

    float *qkv_ptr, *attn_ptr;
    uint32_t *xt, *wqt, *wot;
    cudaGetSymbolAddress((void**)&qkv_ptr, g_qkv);
    cudaGetSymbolAddress((void**)&attn_ptr, g_attn);
    cudaGetSymbolAddress((void**)&xt,  g_xt);
    cudaGetSymbolAddress((void**)&wqt, g_wqkvt);
    cudaGetSymbolAddress((void**)&wot, g_woutt);

    static bool attr_set = false;
    if (!attr_set) {
        cudaFuncSetAttribute(attn_mma,
                             cudaFuncAttributeMaxDynamicSharedMemorySize,
                             ATTN_SMEM);
        cudaFuncSetAttribute(gemm_tf32_v6,
                             cudaFuncAttributeMaxDynamicSharedMemorySize,
                             G6_SMEM);
        attr_set = true;
    }

    // 0) fused prepass
    cvt_all_kernel<<<592, 256>>>(x, w_qkv, w_out);

    {   // 1) QKV projection
        dim3 grid(QKV3 / 128, NROW / 128);
        gemm_tf32_v6<<<grid, 256, G6_SMEM>>>(xt, wqt, b_qkv, qkv_ptr,
                                             NROW, QKV3, D_);
    }
    {   // 2) periodic-causal attention
        dim3 grid(64, B_ * H_);
        attn_mma<<<grid, 256, ATTN_SMEM>>>(periods);
    }
    {   // 3) output projection (g_attn already tf32-rounded)
        dim3 grid(D_ / 128, NROW / 128);
        gemm_tf32_v6<<<grid, 256, G6_SMEM>>>((const uint32_t*)attn_ptr, wot,
                                             b_out, out, NROW, D_, D_);
    }
}